// round 6
// baseline (speedup 1.0000x reference)
#include <cuda_runtime.h>

#define IMG_B 8
#define IMG_H 100
#define IMG_W 100
#define IMG_C 256
#define OUT_HW 7
#define CELLS 49
#define N_ROIS 2000
#define N_CELLS (N_ROIS * CELLS)   // 98000

#define TS 8                        // tile size in pixels
#define TG 13                       // tiles per dim: ceil(100/8)
#define NT (IMG_B * TG * TG)        // 1352 tiles
#define HALO 9                      // tile + 1 halo row/col
#define SMEM_BYTES (HALO * HALO * IMG_C * 4)   // 82944

__device__ int g_count[NT];
__device__ int g_offset[NT];
__device__ int g_fill[NT];
__device__ int g_list[N_CELLS];

// ---- shared coordinate math (must match reference exactly) ----
struct CellGeo {
    int b, ty, by, tx, bx;
    float ly, lx;
    bool valid;
};

__device__ __forceinline__ CellGeo cell_geo(const float* __restrict__ rois, int cell)
{
    int roi = cell / CELLS;
    int rem = cell - roi * CELLS;
    int oy = rem / OUT_HW;
    int ox = rem - oy * OUT_HW;

    const float* r = rois + roi * 5;
    float rb  = __ldg(r + 0);
    float rx1 = __ldg(r + 1);
    float ry1 = __ldg(r + 2);
    float rx2 = __ldg(r + 3);
    float ry2 = __ldg(r + 4);

    float x1 = rx1 * (1.0f / IMG_W);
    float x2 = rx2 * (1.0f / IMG_W);
    float y1 = ry1 * (1.0f / IMG_H);
    float y2 = ry2 * (1.0f / IMG_H);

    float in_y = y1 * (float)(IMG_H - 1)
               + (float)oy * ((y2 - y1) * (float)(IMG_H - 1) / (float)(OUT_HW - 1));
    float in_x = x1 * (float)(IMG_W - 1)
               + (float)ox * ((x2 - x1) * (float)(IMG_W - 1) / (float)(OUT_HW - 1));

    CellGeo g;
    g.b = (int)rb;
    g.valid = (in_y >= 0.0f) && (in_y <= (float)(IMG_H - 1)) &&
              (in_x >= 0.0f) && (in_x <= (float)(IMG_W - 1));

    float fy = floorf(in_y);
    float fx = floorf(in_x);
    g.ly = in_y - fy;
    g.lx = in_x - fx;
    g.ty = min(max((int)fy, 0), IMG_H - 1);
    g.by = min(max((int)ceilf(in_y), 0), IMG_H - 1);
    g.tx = min(max((int)fx, 0), IMG_W - 1);
    g.bx = min(max((int)ceilf(in_x), 0), IMG_W - 1);
    return g;
}

__device__ __forceinline__ int tile_of(const CellGeo& g)
{
    return (g.b * TG + (g.ty >> 3)) * TG + (g.tx >> 3);
}

// ---- pass 0: zero counters ----
__global__ void k_init()
{
    int i = blockIdx.x * blockDim.x + threadIdx.x;
    if (i < NT) g_count[i] = 0;
}

// ---- pass 1: count cells per tile ----
__global__ void k_count(const float* __restrict__ rois)
{
    int cell = blockIdx.x * blockDim.x + threadIdx.x;
    if (cell >= N_CELLS) return;
    CellGeo g = cell_geo(rois, cell);
    atomicAdd(&g_count[tile_of(g)], 1);
}

// ---- pass 2: exclusive scan over NT=1352 counts (1 block, 1024 threads) ----
__global__ void k_scan()
{
    __shared__ int s[1024];
    int t = threadIdx.x;
    int i0 = 2 * t, i1 = 2 * t + 1;
    int c0 = (i0 < NT) ? g_count[i0] : 0;
    int c1 = (i1 < NT) ? g_count[i1] : 0;
    s[t] = c0 + c1;
    __syncthreads();
    #pragma unroll
    for (int d = 1; d < 1024; d <<= 1) {
        int v = (t >= d) ? s[t - d] : 0;
        __syncthreads();
        s[t] += v;
        __syncthreads();
    }
    int excl = s[t] - (c0 + c1);
    if (i0 < NT) { g_offset[i0] = excl;      g_fill[i0] = excl; }
    if (i1 < NT) { g_offset[i1] = excl + c0; g_fill[i1] = excl + c0; }
}

// ---- pass 3: scatter cell ids into per-tile lists ----
__global__ void k_fill(const float* __restrict__ rois)
{
    int cell = blockIdx.x * blockDim.x + threadIdx.x;
    if (cell >= N_CELLS) return;
    CellGeo g = cell_geo(rois, cell);
    int pos = atomicAdd(&g_fill[tile_of(g)], 1);
    g_list[pos] = cell;
}

// ---- pass 4: per-tile processing from smem ----
// Block = 512 threads, one 8x8 tile (+1 halo -> 9x9 pixels x 1KB = 81KB smem).
// Channel split per lane: lo = lane*4 .. lane*4+3 and hi = 128 + lane*4 ..
// -> both smem LDS.128 sweeps are contiguous 512B (conflict-free, 4 cyc).
__global__ void __launch_bounds__(512, 2)
k_process(const float* __restrict__ img,
          const float* __restrict__ rois,
          float* __restrict__ out)
{
    int t = blockIdx.x;
    int cnt = g_count[t];
    if (cnt == 0) return;
    int off = g_offset[t];

    int b   = t / (TG * TG);
    int rr  = t - b * (TG * TG);
    int y0  = (rr / TG) * TS;
    int x0  = (rr % TG) * TS;
    int nrows = min(HALO, IMG_H - y0);
    int ncols = min(HALO, IMG_W - x0);

    extern __shared__ float sm[];   // [HALO*HALO][256]

    // cooperative tile load: each image row segment is ncols*1KB contiguous
    {
        int tid = threadIdx.x;
        int row_f4 = ncols * (IMG_C / 4);   // float4 per row segment
        for (int dy = 0; dy < nrows; dy++) {
            const float4* src = (const float4*)(img
                + ((size_t)(b * IMG_H + y0 + dy) * IMG_W + x0) * IMG_C);
            float4* dst = (float4*)(sm + (size_t)dy * HALO * IMG_C);
            for (int i = tid; i < row_f4; i += 512)
                dst[i] = __ldg(src + i);
        }
    }
    __syncthreads();

    int warp = threadIdx.x >> 5;
    int lane = threadIdx.x & 31;
    int ch_lo = lane * 4;           // floats
    int ch_hi = 128 + lane * 4;

    for (int i = off + warp; i < off + cnt; i += 16) {
        int cell = g_list[i];
        CellGeo g = cell_geo(rois, cell);

        float* ocell = out + (size_t)cell * IMG_C;

        if (!g.valid) {
            float4 z = make_float4(0.f, 0.f, 0.f, 0.f);
            *(float4*)(ocell + ch_lo) = z;
            *(float4*)(ocell + ch_hi) = z;
            continue;
        }

        int sdy_t = g.ty - y0, sdy_b = g.by - y0;
        int sdx_t = g.tx - x0, sdx_b = g.bx - x0;

        const float* s_tl = sm + (size_t)(sdy_t * HALO + sdx_t) * IMG_C;
        const float* s_tr = sm + (size_t)(sdy_t * HALO + sdx_b) * IMG_C;
        const float* s_bl = sm + (size_t)(sdy_b * HALO + sdx_t) * IMG_C;
        const float* s_br = sm + (size_t)(sdy_b * HALO + sdx_b) * IMG_C;

        float lx = g.lx, ly = g.ly;

        #pragma unroll
        for (int h = 0; h < 2; h++) {
            int ch = h ? ch_hi : ch_lo;
            float4 tl = *(const float4*)(s_tl + ch);
            float4 tr = *(const float4*)(s_tr + ch);
            float4 bl = *(const float4*)(s_bl + ch);
            float4 br = *(const float4*)(s_br + ch);
            float4 res;
            {
                float top, bot;
                top = tl.x + (tr.x - tl.x) * lx;
                bot = bl.x + (br.x - bl.x) * lx;
                res.x = top + (bot - top) * ly;
                top = tl.y + (tr.y - tl.y) * lx;
                bot = bl.y + (br.y - bl.y) * lx;
                res.y = top + (bot - top) * ly;
                top = tl.z + (tr.z - tl.z) * lx;
                bot = bl.z + (br.z - bl.z) * lx;
                res.z = top + (bot - top) * ly;
                top = tl.w + (tr.w - tl.w) * lx;
                bot = bl.w + (br.w - bl.w) * lx;
                res.w = top + (bot - top) * ly;
            }
            *(float4*)(ocell + ch) = res;
        }
    }
}

extern "C" void kernel_launch(void* const* d_in, const int* in_sizes, int n_in,
                              void* d_out, int out_size)
{
    const float* img  = (const float*)d_in[0];
    const float* rois = (const float*)d_in[1];
    float* out = (float*)d_out;

    static bool attr_done = false;
    // cudaFuncSetAttribute is a host-side call, not a stream op; idempotent.
    cudaFuncSetAttribute(k_process, cudaFuncAttributeMaxDynamicSharedMemorySize,
                         SMEM_BYTES);

    k_init<<<(NT + 511) / 512, 512>>>();
    k_count<<<(N_CELLS + 511) / 512, 512>>>(rois);
    k_scan<<<1, 1024>>>();
    k_fill<<<(N_CELLS + 511) / 512, 512>>>(rois);
    k_process<<<NT, 512, SMEM_BYTES>>>(img, rois, out);
    (void)attr_done;
}

// round 7
// speedup vs baseline: 1.3268x; 1.3268x over previous
#include <cuda_runtime.h>

#define IMG_B 8
#define IMG_H 100
#define IMG_W 100
#define IMG_C 256
#define OUT_HW 7
#define CELLS 49
#define N_ROIS 2000
#define N_CELLS (N_ROIS * CELLS)   // 98000

#define TS 8                        // tile size (pixels)
#define TG 13                       // tiles per dim
#define NT (IMG_B * TG * TG)        // 1352
#define HALO 9                      // tile + 1 halo
#define CAP 1024                    // max cells per tile list
#define SMEM_BYTES (HALO * HALO * IMG_C * 4)   // 82944

__device__ int g_cnt[NT];
__device__ int g_list[NT * CAP];    // 5.5 MB

// ---- coordinate math (must match reference exactly) ----
struct CellGeo {
    int b, ty, by, tx, bx;
    float ly, lx;
    bool valid;
};

__device__ __forceinline__ CellGeo cell_geo(const float* __restrict__ rois, int cell)
{
    int roi = cell / CELLS;
    int rem = cell - roi * CELLS;
    int oy = rem / OUT_HW;
    int ox = rem - oy * OUT_HW;

    const float* r = rois + roi * 5;
    float rb  = __ldg(r + 0);
    float rx1 = __ldg(r + 1);
    float ry1 = __ldg(r + 2);
    float rx2 = __ldg(r + 3);
    float ry2 = __ldg(r + 4);

    float x1 = rx1 * (1.0f / IMG_W);
    float x2 = rx2 * (1.0f / IMG_W);
    float y1 = ry1 * (1.0f / IMG_H);
    float y2 = ry2 * (1.0f / IMG_H);

    float in_y = y1 * (float)(IMG_H - 1)
               + (float)oy * ((y2 - y1) * (float)(IMG_H - 1) / (float)(OUT_HW - 1));
    float in_x = x1 * (float)(IMG_W - 1)
               + (float)ox * ((x2 - x1) * (float)(IMG_W - 1) / (float)(OUT_HW - 1));

    CellGeo g;
    g.b = (int)rb;
    g.valid = (in_y >= 0.0f) && (in_y <= (float)(IMG_H - 1)) &&
              (in_x >= 0.0f) && (in_x <= (float)(IMG_W - 1));

    float fy = floorf(in_y);
    float fx = floorf(in_x);
    g.ly = in_y - fy;
    g.lx = in_x - fx;
    g.ty = min(max((int)fy, 0), IMG_H - 1);
    g.by = min(max((int)ceilf(in_y), 0), IMG_H - 1);
    g.tx = min(max((int)fx, 0), IMG_W - 1);
    g.bx = min(max((int)ceilf(in_x), 0), IMG_W - 1);
    return g;
}

__device__ __forceinline__ int tile_of(const CellGeo& g)
{
    return (g.b * TG + (g.ty >> 3)) * TG + (g.tx >> 3);
}

// ---- pass 0: zero per-tile counters ----
__global__ void k_zero()
{
    int i = blockIdx.x * blockDim.x + threadIdx.x;
    if (i < NT) g_cnt[i] = 0;
}

// ---- pass 1: bin cells into per-tile lists (single pass, fixed capacity) ----
__global__ void k_bin(const float* __restrict__ rois)
{
    int cell = blockIdx.x * blockDim.x + threadIdx.x;
    if (cell >= N_CELLS) return;
    CellGeo g = cell_geo(rois, cell);
    int t = tile_of(g);
    int pos = atomicAdd(&g_cnt[t], 1);
    if (pos < CAP) g_list[t * CAP + pos] = cell;
}

// ---- pass 2: per-tile processing from smem ----
// 512 threads / block, one 8x8 tile (+1 halo = 9x9 px x 1KB = 81KB smem),
// 2 blocks per SM. Warp-per-cell; channel split lane*16B (conflict-free
// LDS.128) halves at ch 0..127 and 128..255.
__global__ void __launch_bounds__(512, 2)
k_process(const float* __restrict__ img,
          const float* __restrict__ rois,
          float* __restrict__ out)
{
    int t = blockIdx.x;
    int cnt = min(g_cnt[t], CAP);
    if (cnt == 0) return;

    int b   = t / (TG * TG);
    int rr  = t - b * (TG * TG);
    int y0  = (rr / TG) * TS;
    int x0  = (rr % TG) * TS;
    int nrows = min(HALO, IMG_H - y0);
    int ncols = min(HALO, IMG_W - x0);

    extern __shared__ float sm[];   // [HALO rows][HALO px][256 ch], pitch HALO*IMG_C

    // cooperative tile load (flattened): each row segment = ncols KB contiguous
    {
        int row_f4 = ncols * (IMG_C / 4);        // float4 per row segment
        int tot    = nrows * row_f4;
        for (int i = threadIdx.x; i < tot; i += 512) {
            int dy = i / row_f4;
            int j  = i - dy * row_f4;
            const float4* src = (const float4*)(img
                + ((size_t)(b * IMG_H + y0 + dy) * IMG_W + x0) * IMG_C);
            ((float4*)(sm + (size_t)dy * HALO * IMG_C))[j] = __ldg(src + j);
        }
    }
    __syncthreads();

    int warp = threadIdx.x >> 5;
    int lane = threadIdx.x & 31;
    int ch_lo = lane * 4;            // floats; LDS.128 at 16B stride = conflict-free
    int ch_hi = 128 + lane * 4;

    const int* list = g_list + t * CAP;

    for (int i = warp; i < cnt; i += 16) {
        int cell = list[i];
        CellGeo g = cell_geo(rois, cell);

        float* ocell = out + (size_t)cell * IMG_C;

        if (!g.valid) {
            float4 z = make_float4(0.f, 0.f, 0.f, 0.f);
            *(float4*)(ocell + ch_lo) = z;
            *(float4*)(ocell + ch_hi) = z;
            continue;
        }

        int sdy_t = g.ty - y0, sdy_b = g.by - y0;
        int sdx_t = g.tx - x0, sdx_b = g.bx - x0;

        const float* s_tl = sm + (size_t)(sdy_t * HALO + sdx_t) * IMG_C;
        const float* s_tr = sm + (size_t)(sdy_t * HALO + sdx_b) * IMG_C;
        const float* s_bl = sm + (size_t)(sdy_b * HALO + sdx_t) * IMG_C;
        const float* s_br = sm + (size_t)(sdy_b * HALO + sdx_b) * IMG_C;

        float lx = g.lx, ly = g.ly;

        #pragma unroll
        for (int h = 0; h < 2; h++) {
            int ch = h ? ch_hi : ch_lo;
            float4 tl = *(const float4*)(s_tl + ch);
            float4 tr = *(const float4*)(s_tr + ch);
            float4 bl = *(const float4*)(s_bl + ch);
            float4 br = *(const float4*)(s_br + ch);
            float4 res;
            {
                float top, bot;
                top = tl.x + (tr.x - tl.x) * lx;
                bot = bl.x + (br.x - bl.x) * lx;
                res.x = top + (bot - top) * ly;
                top = tl.y + (tr.y - tl.y) * lx;
                bot = bl.y + (br.y - bl.y) * lx;
                res.y = top + (bot - top) * ly;
                top = tl.z + (tr.z - tl.z) * lx;
                bot = bl.z + (br.z - bl.z) * lx;
                res.z = top + (bot - top) * ly;
                top = tl.w + (tr.w - tl.w) * lx;
                bot = bl.w + (br.w - bl.w) * lx;
                res.w = top + (bot - top) * ly;
            }
            *(float4*)(ocell + ch) = res;
        }
    }
}

extern "C" void kernel_launch(void* const* d_in, const int* in_sizes, int n_in,
                              void* d_out, int out_size)
{
    const float* img  = (const float*)d_in[0];
    const float* rois = (const float*)d_in[1];
    float* out = (float*)d_out;

    cudaFuncSetAttribute(k_process, cudaFuncAttributeMaxDynamicSharedMemorySize,
                         SMEM_BYTES);

    k_zero<<<(NT + 511) / 512, 512>>>();
    k_bin<<<(N_CELLS + 255) / 256, 256>>>(rois);
    k_process<<<NT, 512, SMEM_BYTES>>>(img, rois, out);
}